// round 8
// baseline (speedup 1.0000x reference)
#include <cuda_runtime.h>
#include <cuda_bf16.h>
#include <float.h>
#include <stdint.h>

// ---------------------------------------------------------------------------
// Problem dims
// ---------------------------------------------------------------------------
#define N_ROWS 16384     // 32*512
#define K_EMB  8192
#define D_DIM  256
#define NQ_ELEMS (N_ROWS * D_DIM)   // 4194304

// Coarse-kernel tiling
#define BM 128           // rows per CTA
#define BN 256           // codes per col-block
#define NBLK (K_EMB / BN)    // 32
#define KC 128           // K per E-stage chunk
#define NSTAGE (NBLK * 2)    // 64 stages of (blk, kc)
#define XS 264           // X row stride (bf16): 528B -> 4-bank shift per row
#define ES2 136          // E chunk row stride (bf16): 272B -> 4-bank shift
#define MARGIN 3.0f
#define CAND_CAP 64
#define NTHR 256         // 8 warps: 2(m) x 4(n), warp tile 64x64

// ---------------------------------------------------------------------------
// Scratch (device globals; no allocations allowed)
// ---------------------------------------------------------------------------
__device__ float          g_enorm[K_EMB];
__device__ int            g_indices[N_ROWS];
__device__ float          g_partial[2048];
__device__ __nv_bfloat16  g_Xb[NQ_ELEMS];
__device__ __nv_bfloat16  g_Eb[K_EMB * D_DIM];
__device__ int            g_candcnt[N_ROWS];
__device__ int            g_cand[N_ROWS * CAND_CAP];

// ---------------------------------------------------------------------------
// Helpers
// ---------------------------------------------------------------------------
__device__ __forceinline__ unsigned enc_f(float f) {
    unsigned u = __float_as_uint(f);
    return (u & 0x80000000u) ? ~u : (u | 0x80000000u);
}
__device__ __forceinline__ float dec_f(unsigned k) {
    return (k & 0x80000000u) ? __uint_as_float(k & 0x7FFFFFFFu)
                             : __uint_as_float(~k);
}

__device__ __forceinline__ void cp_async16(void* smem_dst, const void* gsrc) {
    unsigned saddr = (unsigned)__cvta_generic_to_shared(smem_dst);
    asm volatile("cp.async.cg.shared.global [%0], [%1], 16;"
                 :: "r"(saddr), "l"(gsrc) : "memory");
}
__device__ __forceinline__ void cp_commit() {
    asm volatile("cp.async.commit_group;" ::: "memory");
}
__device__ __forceinline__ void cp_wait0() {
    asm volatile("cp.async.wait_group 0;" ::: "memory");
}

__device__ __forceinline__ void ldmat4(uint32_t* r, uint32_t addr) {
    asm volatile("ldmatrix.sync.aligned.m8n8.x4.shared.b16 {%0,%1,%2,%3}, [%4];"
                 : "=r"(r[0]), "=r"(r[1]), "=r"(r[2]), "=r"(r[3]) : "r"(addr));
}

__device__ __forceinline__ void mma_bf16(float* d, const uint32_t* a,
                                         uint32_t b0, uint32_t b1) {
    asm volatile(
        "mma.sync.aligned.m16n8k16.row.col.f32.bf16.bf16.f32 "
        "{%0,%1,%2,%3}, {%4,%5,%6,%7}, {%8,%9}, {%0,%1,%2,%3};"
        : "+f"(d[0]), "+f"(d[1]), "+f"(d[2]), "+f"(d[3])
        : "r"(a[0]), "r"(a[1]), "r"(a[2]), "r"(a[3]), "r"(b0), "r"(b1));
}

// ---------------------------------------------------------------------------
// Kernel A: fp32 -> bf16 (rn). n4 = n/4.
// ---------------------------------------------------------------------------
__global__ void vq_tobf16_kernel(const float* __restrict__ src,
                                 __nv_bfloat16* __restrict__ dst, int n4) {
    int i = blockIdx.x * blockDim.x + threadIdx.x;
    if (i >= n4) return;
    float4 v = reinterpret_cast<const float4*>(src)[i];
    __nv_bfloat162* d2 = reinterpret_cast<__nv_bfloat162*>(dst);
    d2[2 * i + 0] = __floats2bfloat162_rn(v.x, v.y);
    d2[2 * i + 1] = __floats2bfloat162_rn(v.z, v.w);
}

// ---------------------------------------------------------------------------
// Kernel B: ||e_k||^2 (fp32) + zero candidate counters.
// ---------------------------------------------------------------------------
__global__ void vq_enorm_kernel(const float* __restrict__ emb) {
    int gt = blockIdx.x * blockDim.x + threadIdx.x;
    if (gt < N_ROWS) g_candcnt[gt] = 0;
    int gw   = gt >> 5;
    int lane = threadIdx.x & 31;
    if (gw >= K_EMB) return;
    const float4* e4 = reinterpret_cast<const float4*>(emb + (size_t)gw * D_DIM);
    float s = 0.f;
#pragma unroll
    for (int i = 0; i < 2; ++i) {
        float4 v = e4[lane + 32 * i];
        s += v.x * v.x + v.y * v.y + v.z * v.z + v.w * v.w;
    }
#pragma unroll
    for (int off = 16; off >= 1; off >>= 1)
        s += __shfl_xor_sync(0xffffffffu, s, off);
    if (lane == 0) g_enorm[gw] = s;
}

// ---------------------------------------------------------------------------
// Kernel C: coarse bf16 GEMM + row-min + candidate collection.
// Grid = 128 CTAs, 256 threads (8 warps: 2m x 4n). Warp tile 64x64.
// Per ks: 8 LDSM (4KB) -> 32 HMMA (65536 MACs): tensor-dominant by 1.75x.
// ---------------------------------------------------------------------------
__global__ void __launch_bounds__(NTHR, 1)
vq_coarse_kernel() {
    extern __shared__ __align__(16) char smem[];
    __nv_bfloat16* Xs  = reinterpret_cast<__nv_bfloat16*>(smem);          // [128][XS]
    __nv_bfloat16* Es0 = Xs + BM * XS;                                    // [256][ES2]
    __nv_bfloat16* Es1 = Es0 + BN * ES2;                                  // [256][ES2]
    float*    ensS    = reinterpret_cast<float*>(Es1 + BN * ES2);         // [2][256]
    unsigned* rowminS = reinterpret_cast<unsigned*>(ensS + 2 * BN);       // [128]

    const int tid  = threadIdx.x;
    const int warp = tid >> 5;
    const int lane = tid & 31;
    const int wm   = warp >> 2;      // 0..1 -> rows wm*64
    const int wn   = warp & 3;       // 0..3 -> cols wn*64
    const int rowbase = blockIdx.x * BM;
    const int lrow4 = lane >> 2;     // 0..7
    const int lcol2 = (lane & 3) * 2;

    // Resident X tile [128][256] bf16 (padded rows): 4096 float4s.
#pragma unroll
    for (int t = 0; t < 16; ++t) {
        int idx = tid + t * NTHR;            // 0..4095
        int r = idx >> 5, c8 = idx & 31;     // 128 rows x 32 float4
        float4 v = *reinterpret_cast<const float4*>(g_Xb + (size_t)(rowbase + r) * D_DIM + c8 * 8);
        *reinterpret_cast<float4*>(Xs + r * XS + c8 * 8) = v;
    }
    if (tid < BM) rowminS[tid] = 0xFFFFFFFFu;

    // Stage = (blk, kc). Loads E chunk [256 codes][128 K bf16] into buffer s.
    auto load_stage = [&](int stage, int s) {
        const int blk = stage >> 1, kc = stage & 1;
        __nv_bfloat16* dst = s ? Es1 : Es0;
        const __nv_bfloat16* src = g_Eb + (size_t)blk * BN * D_DIM + kc * KC;
#pragma unroll
        for (int t = 0; t < 16; ++t) {
            int idx = tid + t * NTHR;        // 0..4095
            int r = idx >> 4, c8 = idx & 15; // 256 rows x 16 float4
            cp_async16(dst + r * ES2 + c8 * 8, src + (size_t)r * D_DIM + c8 * 8);
        }
        if (kc == 0 && tid < 64)
            cp_async16(&ensS[(blk & 1) * BN + tid * 4], &g_enorm[blk * BN + tid * 4]);
    };

    load_stage(0, 0);
    cp_commit();

    // ldmatrix lane addressing
    const uint32_t sXs  = (uint32_t)__cvta_generic_to_shared(Xs);
    const uint32_t sEs0 = (uint32_t)__cvta_generic_to_shared(Es0);
    const uint32_t sEs1 = (uint32_t)__cvta_generic_to_shared(Es1);
    const int lrow16 = lane & 15;
    const int khalf  = (lane & 16) ? 16 : 0;   // bytes
    uint32_t aA[4];
#pragma unroll
    for (int mt = 0; mt < 4; ++mt)
        aA[mt] = sXs + (uint32_t)((wm * 64 + mt * 16 + lrow16) * XS * 2) + khalf;
    uint32_t aBb[4];
#pragma unroll
    for (int n2 = 0; n2 < 4; ++n2)
        aBb[n2] = (uint32_t)((wn * 64 + n2 * 16 + lrow16) * ES2 * 2) + khalf;

    float acc[4][8][4];   // [mt 16-row][nt 8-col][frag]

    for (int stage = 0; stage < NSTAGE; ++stage) {
        const int blk = stage >> 1, kc = stage & 1;
        const int s = stage & 1;   // buffer parity == stage parity
        cp_wait0();
        __syncthreads();   // stage data ready; all warps done with other buffer
        if (stage + 1 < NSTAGE) { load_stage(stage + 1, s ^ 1); cp_commit(); }

        if (kc == 0) {
#pragma unroll
            for (int mt = 0; mt < 4; ++mt)
#pragma unroll
                for (int nt = 0; nt < 8; ++nt)
#pragma unroll
                    for (int i = 0; i < 4; ++i) acc[mt][nt][i] = 0.f;
        }

        const uint32_t sEb = s ? sEs1 : sEs0;
        const uint32_t aX0 = (uint32_t)(kc * KC * 2);   // byte offset in X row

#pragma unroll
        for (int ks = 0; ks < 8; ++ks) {
            const uint32_t kb = (uint32_t)ks * 32;   // 16 bf16 = 32B
            uint32_t A[4][4];
#pragma unroll
            for (int mt = 0; mt < 4; ++mt) ldmat4(A[mt], aA[mt] + aX0 + kb);
            uint32_t B[4][4];
#pragma unroll
            for (int n2 = 0; n2 < 4; ++n2) ldmat4(B[n2], sEb + aBb[n2] + kb);
#pragma unroll
            for (int mt = 0; mt < 4; ++mt)
#pragma unroll
                for (int n2 = 0; n2 < 4; ++n2) {
                    mma_bf16(acc[mt][n2 * 2 + 0], A[mt], B[n2][0], B[n2][2]);
                    mma_bf16(acc[mt][n2 * 2 + 1], A[mt], B[n2][1], B[n2][3]);
                }
        }

        if (kc == 0) continue;

        // ------- Epilogue for block blk -------
        float e2[8][2];
#pragma unroll
        for (int nt = 0; nt < 8; ++nt) {
            int c = wn * 64 + nt * 8 + lcol2;
            e2[nt][0] = ensS[(blk & 1) * BN + c];
            e2[nt][1] = ensS[(blk & 1) * BN + c + 1];
        }
        float smin[8];
#pragma unroll
        for (int sl = 0; sl < 8; ++sl) smin[sl] = FLT_MAX;
#pragma unroll
        for (int mt = 0; mt < 4; ++mt)
#pragma unroll
            for (int nt = 0; nt < 8; ++nt)
#pragma unroll
                for (int i = 0; i < 4; ++i) {
                    float d = fmaf(-2.0f, acc[mt][nt][i], e2[nt][i & 1]);
                    acc[mt][nt][i] = d;
                    int sl = mt * 2 + (i >> 1);
                    smin[sl] = fminf(smin[sl], d);
                }
        float tmin[8];
#pragma unroll
        for (int sl = 0; sl < 8; ++sl) tmin[sl] = smin[sl];
#pragma unroll
        for (int sl = 0; sl < 8; ++sl) {
            smin[sl] = fminf(smin[sl], __shfl_xor_sync(0xffffffffu, smin[sl], 1));
            smin[sl] = fminf(smin[sl], __shfl_xor_sync(0xffffffffu, smin[sl], 2));
        }
        if ((lane & 3) == 0) {
#pragma unroll
            for (int sl = 0; sl < 8; ++sl) {
                int lr = wm * 64 + (sl >> 1) * 16 + lrow4 + 8 * (sl & 1);
                atomicMin(&rowminS[lr], enc_f(smin[sl]));
            }
        }
        __syncthreads();   // rowmin visible -> tight thresholds
        float thr[8];
        bool any = false;
#pragma unroll
        for (int sl = 0; sl < 8; ++sl) {
            int lr = wm * 64 + (sl >> 1) * 16 + lrow4 + 8 * (sl & 1);
            thr[sl] = dec_f(rowminS[lr]) + MARGIN;
            any |= (tmin[sl] < thr[sl]);
        }
        if (any) {
#pragma unroll
            for (int mt = 0; mt < 4; ++mt)
#pragma unroll
                for (int nt = 0; nt < 8; ++nt)
#pragma unroll
                    for (int i = 0; i < 4; ++i) {
                        int sl = mt * 2 + (i >> 1);
                        if (acc[mt][nt][i] < thr[sl]) {
                            int lr = wm * 64 + mt * 16 + lrow4 + 8 * (i >> 1);
                            int grow = rowbase + lr;
                            int gcol = blk * BN + wn * 64 + nt * 8 + lcol2 + (i & 1);
                            int pos = atomicAdd(&g_candcnt[grow], 1);
                            if (pos < CAND_CAP) g_cand[grow * CAND_CAP + pos] = gcol;
                        }
                    }
        }
    }
}

// ---------------------------------------------------------------------------
// Kernel D: exact fp32 rescue over candidates. One warp per row.
// ---------------------------------------------------------------------------
__global__ void vq_rescue_kernel(const float* __restrict__ X,
                                 const float* __restrict__ E) {
    int warp = threadIdx.x >> 5;
    int lane = threadIdx.x & 31;
    int row  = blockIdx.x * 8 + warp;

    const float4* x4 = reinterpret_cast<const float4*>(X + (size_t)row * D_DIM);
    float4 xa = x4[lane];
    float4 xb = x4[lane + 32];

    int cnt = g_candcnt[row];
    float best = FLT_MAX;
    int   bidx = 0x7fffffff;

    auto eval = [&](int idx) {
        const float4* e4 = reinterpret_cast<const float4*>(E + (size_t)idx * D_DIM);
        float4 ea = e4[lane];
        float4 eb = e4[lane + 32];
        float p = xa.x * ea.x + xa.y * ea.y + xa.z * ea.z + xa.w * ea.w
                + xb.x * eb.x + xb.y * eb.y + xb.z * eb.z + xb.w * eb.w;
#pragma unroll
        for (int off = 16; off >= 1; off >>= 1)
            p += __shfl_xor_sync(0xffffffffu, p, off);
        float dist = g_enorm[idx] - 2.0f * p;
        if (dist < best || (dist == best && idx < bidx)) { best = dist; bidx = idx; }
    };

    if (cnt > 0 && cnt <= CAND_CAP) {
        for (int c = 0; c < cnt; ++c) eval(g_cand[row * CAND_CAP + c]);
    } else {
        for (int k = 0; k < K_EMB; ++k) eval(k);   // overflow fallback (rare)
    }
    if (lane == 0) g_indices[row] = bidx;
}

// ---------------------------------------------------------------------------
// Kernel E: gather quantized rows + partial loss sums.
// ---------------------------------------------------------------------------
__global__ void vq_gather_kernel(const float* __restrict__ X,
                                 const float* __restrict__ E,
                                 float* __restrict__ out_q,
                                 float* __restrict__ out_idx_f,
                                 int*   __restrict__ out_idx_i) {
    __shared__ float wsum[8];
    int warp = threadIdx.x >> 5;
    int lane = threadIdx.x & 31;
    int row  = blockIdx.x * 8 + warp;

    int idx = g_indices[row];
    const float4* x4 = reinterpret_cast<const float4*>(X + (size_t)row * D_DIM);
    const float4* e4 = reinterpret_cast<const float4*>(E + (size_t)idx * D_DIM);

    float s = 0.f;
#pragma unroll
    for (int t = 0; t < 2; ++t) {
        int c = lane + 32 * t;
        float4 xv = x4[c];
        float4 ev = e4[c];
        if (out_q) reinterpret_cast<float4*>(out_q + (size_t)row * D_DIM)[c] = ev;
        float dx = ev.x - xv.x, dy = ev.y - xv.y, dz = ev.z - xv.z, dw = ev.w - xv.w;
        s += dx * dx + dy * dy + dz * dz + dw * dw;
    }
#pragma unroll
    for (int off = 16; off >= 1; off >>= 1)
        s += __shfl_xor_sync(0xffffffffu, s, off);
    if (lane == 0) {
        wsum[warp] = s;
        if (out_idx_f) out_idx_f[row] = (float)idx;
        if (out_idx_i) out_idx_i[row] = idx;
    }
    __syncthreads();
    if (threadIdx.x == 0) {
        float t = 0.f;
#pragma unroll
        for (int w = 0; w < 8; ++w) t += wsum[w];
        g_partial[blockIdx.x] = t;
    }
}

// ---------------------------------------------------------------------------
// Kernel F: loss = m + 0.25*m, m = sum/NQ.
// ---------------------------------------------------------------------------
__global__ void vq_loss_kernel(float* __restrict__ out_loss) {
    __shared__ float red[256];
    float s = 0.f;
#pragma unroll
    for (int t = 0; t < 8; ++t) s += g_partial[threadIdx.x + t * 256];
    red[threadIdx.x] = s;
    __syncthreads();
    for (int off = 128; off >= 1; off >>= 1) {
        if (threadIdx.x < off) red[threadIdx.x] += red[threadIdx.x + off];
        __syncthreads();
    }
    if (threadIdx.x == 0) {
        float m = red[0] / (float)NQ_ELEMS;
        *out_loss = m + 0.25f * m;
    }
}

// ---------------------------------------------------------------------------
extern "C" void kernel_launch(void* const* d_in, const int* in_sizes, int n_in,
                              void* d_out, int out_size) {
    const float* X = (const float*)d_in[0];
    const float* E = (const float*)d_in[1];
    float* out = (float*)d_out;

    float* out_q     = nullptr;
    float* out_loss  = nullptr;
    float* out_idx_f = nullptr;
    int*   out_idx_i = nullptr;

    if (out_size == NQ_ELEMS) {
        out_q = out;
    } else if (out_size == NQ_ELEMS + 1) {
        out_q = out; out_loss = out + NQ_ELEMS;
    } else if (out_size == NQ_ELEMS + 1 + N_ROWS) {
        out_q = out; out_loss = out + NQ_ELEMS; out_idx_f = out + NQ_ELEMS + 1;
    } else if (out_size == NQ_ELEMS + N_ROWS) {
        out_q = out; out_idx_f = out + NQ_ELEMS;
    } else if (out_size == N_ROWS) {
        out_idx_i = (int*)d_out;
    } else {
        out_q = out;
    }

    __nv_bfloat16 *dXb, *dEb;
    cudaGetSymbolAddress((void**)&dXb, g_Xb);
    cudaGetSymbolAddress((void**)&dEb, g_Eb);

    // A) bf16 copies
    vq_tobf16_kernel<<<NQ_ELEMS / 4 / 256, 256>>>(X, dXb, NQ_ELEMS / 4);
    vq_tobf16_kernel<<<K_EMB * D_DIM / 4 / 256, 256>>>(E, dEb, K_EMB * D_DIM / 4);

    // B) codebook norms + zero cand counters
    vq_enorm_kernel<<<K_EMB / 8, 256>>>(E);

    // C) coarse bf16 mma + candidate collection
    const int smem_bytes = BM * XS * 2 + 2 * BN * ES2 * 2 + 2 * BN * 4 + BM * 4;
    cudaFuncSetAttribute(vq_coarse_kernel,
                         cudaFuncAttributeMaxDynamicSharedMemorySize, smem_bytes);
    vq_coarse_kernel<<<N_ROWS / BM, NTHR, smem_bytes>>>();

    // D) exact fp32 rescue
    vq_rescue_kernel<<<N_ROWS / 8, 256>>>(X, E);

    // E) gather + partial loss sums
    vq_gather_kernel<<<N_ROWS / 8, 256>>>(X, E, out_q, out_idx_f, out_idx_i);

    // F) loss scalar
    if (out_loss) vq_loss_kernel<<<1, 256>>>(out_loss);
}

// round 9
// speedup vs baseline: 1.2336x; 1.2336x over previous
#include <cuda_runtime.h>
#include <cuda_bf16.h>
#include <float.h>
#include <stdint.h>

// ---------------------------------------------------------------------------
// Problem dims
// ---------------------------------------------------------------------------
#define N_ROWS 16384     // 32*512
#define K_EMB  8192
#define D_DIM  256
#define NQ_ELEMS (N_ROWS * D_DIM)   // 4194304

// Coarse-kernel tiling: grid (128 row-blocks x 2 codebook halves)
#define BM 128           // rows per CTA
#define BN 128           // codes per block
#define KC 64            // K dims per stage chunk
#define BLK_PER_CTA 32   // 4096 codes per CTA (half the codebook)
#define NSTAGE (BLK_PER_CTA * 4)   // 128 stages (4 chunks per block)
#define XS 264           // X row stride (bf16): 528B -> 4-bank shift per row
#define ES 72            // E chunk row stride (bf16): 144B -> 4-bank shift
#define MARGIN 3.0f
#define CAND_CAP 64
#define NTHR 256         // 8 warps: 4(m) x 2(n), warp tile 32x64

// ---------------------------------------------------------------------------
// Scratch (device globals; no allocations allowed)
// ---------------------------------------------------------------------------
__device__ float          g_enorm[K_EMB];
__device__ int            g_indices[N_ROWS];
__device__ float          g_partial[2048];
__device__ __nv_bfloat16  g_Xb[NQ_ELEMS];
__device__ __nv_bfloat16  g_Eb[K_EMB * D_DIM];
__device__ int            g_candcnt[N_ROWS];
__device__ int            g_cand[N_ROWS * CAND_CAP];

// ---------------------------------------------------------------------------
// Helpers
// ---------------------------------------------------------------------------
__device__ __forceinline__ unsigned enc_f(float f) {
    unsigned u = __float_as_uint(f);
    return (u & 0x80000000u) ? ~u : (u | 0x80000000u);
}
__device__ __forceinline__ float dec_f(unsigned k) {
    return (k & 0x80000000u) ? __uint_as_float(k & 0x7FFFFFFFu)
                             : __uint_as_float(~k);
}

__device__ __forceinline__ void cp_async16(void* smem_dst, const void* gsrc) {
    unsigned saddr = (unsigned)__cvta_generic_to_shared(smem_dst);
    asm volatile("cp.async.cg.shared.global [%0], [%1], 16;"
                 :: "r"(saddr), "l"(gsrc) : "memory");
}
__device__ __forceinline__ void cp_commit() {
    asm volatile("cp.async.commit_group;" ::: "memory");
}
__device__ __forceinline__ void cp_wait0() {
    asm volatile("cp.async.wait_group 0;" ::: "memory");
}

__device__ __forceinline__ void ldmat4(uint32_t* r, uint32_t addr) {
    asm volatile("ldmatrix.sync.aligned.m8n8.x4.shared.b16 {%0,%1,%2,%3}, [%4];"
                 : "=r"(r[0]), "=r"(r[1]), "=r"(r[2]), "=r"(r[3]) : "r"(addr));
}

__device__ __forceinline__ void mma_bf16(float* d, const uint32_t* a,
                                         uint32_t b0, uint32_t b1) {
    asm volatile(
        "mma.sync.aligned.m16n8k16.row.col.f32.bf16.bf16.f32 "
        "{%0,%1,%2,%3}, {%4,%5,%6,%7}, {%8,%9}, {%0,%1,%2,%3};"
        : "+f"(d[0]), "+f"(d[1]), "+f"(d[2]), "+f"(d[3])
        : "r"(a[0]), "r"(a[1]), "r"(a[2]), "r"(a[3]), "r"(b0), "r"(b1));
}

// ---------------------------------------------------------------------------
// Kernel A: fp32 -> bf16 (rn). n4 = n/4.
// ---------------------------------------------------------------------------
__global__ void vq_tobf16_kernel(const float* __restrict__ src,
                                 __nv_bfloat16* __restrict__ dst, int n4) {
    int i = blockIdx.x * blockDim.x + threadIdx.x;
    if (i >= n4) return;
    float4 v = reinterpret_cast<const float4*>(src)[i];
    __nv_bfloat162* d2 = reinterpret_cast<__nv_bfloat162*>(dst);
    d2[2 * i + 0] = __floats2bfloat162_rn(v.x, v.y);
    d2[2 * i + 1] = __floats2bfloat162_rn(v.z, v.w);
}

// ---------------------------------------------------------------------------
// Kernel B: ||e_k||^2 (fp32) + zero candidate counters.
// ---------------------------------------------------------------------------
__global__ void vq_enorm_kernel(const float* __restrict__ emb) {
    int gt = blockIdx.x * blockDim.x + threadIdx.x;
    if (gt < N_ROWS) g_candcnt[gt] = 0;
    int gw   = gt >> 5;
    int lane = threadIdx.x & 31;
    if (gw >= K_EMB) return;
    const float4* e4 = reinterpret_cast<const float4*>(emb + (size_t)gw * D_DIM);
    float s = 0.f;
#pragma unroll
    for (int i = 0; i < 2; ++i) {
        float4 v = e4[lane + 32 * i];
        s += v.x * v.x + v.y * v.y + v.z * v.z + v.w * v.w;
    }
#pragma unroll
    for (int off = 16; off >= 1; off >>= 1)
        s += __shfl_xor_sync(0xffffffffu, s, off);
    if (lane == 0) g_enorm[gw] = s;
}

// ---------------------------------------------------------------------------
// Kernel C: coarse bf16 GEMM + row-min + candidate collection.
// Grid = (128 row-blocks, 2 codebook halves), 256 threads (8 warps: 4m x 2n),
// warp tile 32x64. 2 CTAs/SM: independent barrier domains fill pipe bubbles.
// ---------------------------------------------------------------------------
__global__ void __launch_bounds__(NTHR, 2)
vq_coarse_kernel() {
    extern __shared__ __align__(16) char smem[];
    __nv_bfloat16* Xs  = reinterpret_cast<__nv_bfloat16*>(smem);          // [128][XS]
    __nv_bfloat16* Es0 = Xs + BM * XS;                                    // [128][ES]
    __nv_bfloat16* Es1 = Es0 + BN * ES;                                   // [128][ES]
    float*    ensS    = reinterpret_cast<float*>(Es1 + BN * ES);          // [2][128]
    unsigned* rowminS = reinterpret_cast<unsigned*>(ensS + 2 * BN);       // [128]

    const int tid  = threadIdx.x;
    const int warp = tid >> 5;
    const int lane = tid & 31;
    const int wm   = warp >> 1;      // 0..3 -> rows wm*32
    const int wn   = warp & 1;       // 0..1 -> cols wn*64
    const int rowbase = blockIdx.x * BM;
    const int kbase   = blockIdx.y * (BLK_PER_CTA * BN);   // codebook half
    const int lrow4 = lane >> 2;     // 0..7
    const int lcol2 = (lane & 3) * 2;

    // Resident X tile [128][256] bf16 (padded rows): 4096 float4s.
#pragma unroll
    for (int t = 0; t < 16; ++t) {
        int idx = tid + t * NTHR;            // 0..4095
        int r = idx >> 5, c8 = idx & 31;     // 128 rows x 32 float4
        float4 v = *reinterpret_cast<const float4*>(g_Xb + (size_t)(rowbase + r) * D_DIM + c8 * 8);
        *reinterpret_cast<float4*>(Xs + r * XS + c8 * 8) = v;
    }
    if (tid < BM) rowminS[tid] = 0xFFFFFFFFu;

    // Stage = (blk_local, kc). Loads E chunk [128 codes][64 K bf16]:
    // 128 rows x 8 float4 = 1024 float4s, 4 per thread.
    auto load_stage = [&](int stage, int s) {
        const int blk = stage >> 2, kc = stage & 3;
        __nv_bfloat16* dst = s ? Es1 : Es0;
        const __nv_bfloat16* src = g_Eb + (size_t)(kbase + blk * BN) * D_DIM + kc * KC;
#pragma unroll
        for (int t = 0; t < 4; ++t) {
            int idx = tid + t * NTHR;        // 0..1023
            int r = idx >> 3, c8 = idx & 7;  // 128 rows x 8 float4
            cp_async16(dst + r * ES + c8 * 8, src + (size_t)r * D_DIM + c8 * 8);
        }
        if (kc == 0 && tid < 32)
            cp_async16(&ensS[(blk & 1) * BN + tid * 4],
                       &g_enorm[kbase + blk * BN + tid * 4]);
    };

    load_stage(0, 0);
    cp_commit();

    // ldmatrix lane addressing
    const uint32_t sXs  = (uint32_t)__cvta_generic_to_shared(Xs);
    const uint32_t sEs0 = (uint32_t)__cvta_generic_to_shared(Es0);
    const uint32_t sEs1 = (uint32_t)__cvta_generic_to_shared(Es1);
    const int lrow16 = lane & 15;
    const int kh16   = (lane & 16) ? 16 : 0;   // k-half byte offset
    uint32_t aA[2];
#pragma unroll
    for (int mt = 0; mt < 2; ++mt)
        aA[mt] = sXs + (uint32_t)((wm * 32 + mt * 16 + lrow16) * XS * 2) + kh16;
    uint32_t aBb[4];
#pragma unroll
    for (int n2 = 0; n2 < 4; ++n2)
        aBb[n2] = (uint32_t)((wn * 64 + n2 * 16 + lrow16) * ES * 2) + kh16;

    float acc[2][8][4];   // [mt 16-row][nt 8-col][frag]

    for (int stage = 0; stage < NSTAGE; ++stage) {
        const int blk = stage >> 2, kc = stage & 3;
        const int s = stage & 1;   // buffer parity
        cp_wait0();
        __syncthreads();   // stage data ready; all warps done with other buffer
        if (stage + 1 < NSTAGE) { load_stage(stage + 1, s ^ 1); cp_commit(); }

        if (kc == 0) {
#pragma unroll
            for (int mt = 0; mt < 2; ++mt)
#pragma unroll
                for (int nt = 0; nt < 8; ++nt)
#pragma unroll
                    for (int i = 0; i < 4; ++i) acc[mt][nt][i] = 0.f;
        }

        const uint32_t sEb = s ? sEs1 : sEs0;
        const uint32_t aX0 = (uint32_t)(kc * KC * 2);   // byte offset in X row

#pragma unroll
        for (int ks = 0; ks < 4; ++ks) {
            const uint32_t kb = (uint32_t)ks * 32;   // 16 bf16 = 32B
            uint32_t A[2][4];
            ldmat4(A[0], aA[0] + aX0 + kb);
            ldmat4(A[1], aA[1] + aX0 + kb);
            uint32_t B[4][4];
#pragma unroll
            for (int n2 = 0; n2 < 4; ++n2) ldmat4(B[n2], sEb + aBb[n2] + kb);
#pragma unroll
            for (int mt = 0; mt < 2; ++mt)
#pragma unroll
                for (int n2 = 0; n2 < 4; ++n2) {
                    mma_bf16(acc[mt][n2 * 2 + 0], A[mt], B[n2][0], B[n2][2]);
                    mma_bf16(acc[mt][n2 * 2 + 1], A[mt], B[n2][1], B[n2][3]);
                }
        }

        if (kc != 3) continue;

        // ------- Epilogue for block blk -------
        float e2[8][2];
#pragma unroll
        for (int nt = 0; nt < 8; ++nt) {
            int c = wn * 64 + nt * 8 + lcol2;
            e2[nt][0] = ensS[(blk & 1) * BN + c];
            e2[nt][1] = ensS[(blk & 1) * BN + c + 1];
        }
        float smin[4] = {FLT_MAX, FLT_MAX, FLT_MAX, FLT_MAX};
#pragma unroll
        for (int mt = 0; mt < 2; ++mt)
#pragma unroll
            for (int nt = 0; nt < 8; ++nt)
#pragma unroll
                for (int i = 0; i < 4; ++i) {
                    float d = fmaf(-2.0f, acc[mt][nt][i], e2[nt][i & 1]);
                    acc[mt][nt][i] = d;
                    int sl = mt * 2 + (i >> 1);
                    smin[sl] = fminf(smin[sl], d);
                }
        float tmin[4];
#pragma unroll
        for (int sl = 0; sl < 4; ++sl) tmin[sl] = smin[sl];
#pragma unroll
        for (int sl = 0; sl < 4; ++sl) {
            smin[sl] = fminf(smin[sl], __shfl_xor_sync(0xffffffffu, smin[sl], 1));
            smin[sl] = fminf(smin[sl], __shfl_xor_sync(0xffffffffu, smin[sl], 2));
        }
        if ((lane & 3) == 0) {
#pragma unroll
            for (int sl = 0; sl < 4; ++sl) {
                int lr = wm * 32 + (sl >> 1) * 16 + lrow4 + 8 * (sl & 1);
                atomicMin(&rowminS[lr], enc_f(smin[sl]));
            }
        }
        __syncthreads();   // rowmin visible -> tight thresholds
        float thr[4];
        bool any = false;
#pragma unroll
        for (int sl = 0; sl < 4; ++sl) {
            int lr = wm * 32 + (sl >> 1) * 16 + lrow4 + 8 * (sl & 1);
            thr[sl] = dec_f(rowminS[lr]) + MARGIN;
            any |= (tmin[sl] < thr[sl]);
        }
        if (any) {
#pragma unroll
            for (int mt = 0; mt < 2; ++mt)
#pragma unroll
                for (int nt = 0; nt < 8; ++nt)
#pragma unroll
                    for (int i = 0; i < 4; ++i) {
                        int sl = mt * 2 + (i >> 1);
                        if (acc[mt][nt][i] < thr[sl]) {
                            int lr = wm * 32 + mt * 16 + lrow4 + 8 * (i >> 1);
                            int grow = rowbase + lr;
                            int gcol = kbase + blk * BN + wn * 64 + nt * 8 + lcol2 + (i & 1);
                            int pos = atomicAdd(&g_candcnt[grow], 1);
                            if (pos < CAND_CAP) g_cand[grow * CAND_CAP + pos] = gcol;
                        }
                    }
        }
    }
}

// ---------------------------------------------------------------------------
// Kernel D: exact fp32 rescue over candidates. One warp per row.
// ---------------------------------------------------------------------------
__global__ void vq_rescue_kernel(const float* __restrict__ X,
                                 const float* __restrict__ E) {
    int warp = threadIdx.x >> 5;
    int lane = threadIdx.x & 31;
    int row  = blockIdx.x * 8 + warp;

    const float4* x4 = reinterpret_cast<const float4*>(X + (size_t)row * D_DIM);
    float4 xa = x4[lane];
    float4 xb = x4[lane + 32];

    int cnt = g_candcnt[row];
    float best = FLT_MAX;
    int   bidx = 0x7fffffff;

    auto eval = [&](int idx) {
        const float4* e4 = reinterpret_cast<const float4*>(E + (size_t)idx * D_DIM);
        float4 ea = e4[lane];
        float4 eb = e4[lane + 32];
        float p = xa.x * ea.x + xa.y * ea.y + xa.z * ea.z + xa.w * ea.w
                + xb.x * eb.x + xb.y * eb.y + xb.z * eb.z + xb.w * eb.w;
#pragma unroll
        for (int off = 16; off >= 1; off >>= 1)
            p += __shfl_xor_sync(0xffffffffu, p, off);
        float dist = g_enorm[idx] - 2.0f * p;
        if (dist < best || (dist == best && idx < bidx)) { best = dist; bidx = idx; }
    };

    if (cnt > 0 && cnt <= CAND_CAP) {
        for (int c = 0; c < cnt; ++c) eval(g_cand[row * CAND_CAP + c]);
    } else {
        for (int k = 0; k < K_EMB; ++k) eval(k);   // overflow fallback (rare)
    }
    if (lane == 0) g_indices[row] = bidx;
}

// ---------------------------------------------------------------------------
// Kernel E: gather quantized rows + partial loss sums.
// ---------------------------------------------------------------------------
__global__ void vq_gather_kernel(const float* __restrict__ X,
                                 const float* __restrict__ E,
                                 float* __restrict__ out_q,
                                 float* __restrict__ out_idx_f,
                                 int*   __restrict__ out_idx_i) {
    __shared__ float wsum[8];
    int warp = threadIdx.x >> 5;
    int lane = threadIdx.x & 31;
    int row  = blockIdx.x * 8 + warp;

    int idx = g_indices[row];
    const float4* x4 = reinterpret_cast<const float4*>(X + (size_t)row * D_DIM);
    const float4* e4 = reinterpret_cast<const float4*>(E + (size_t)idx * D_DIM);

    float s = 0.f;
#pragma unroll
    for (int t = 0; t < 2; ++t) {
        int c = lane + 32 * t;
        float4 xv = x4[c];
        float4 ev = e4[c];
        if (out_q) reinterpret_cast<float4*>(out_q + (size_t)row * D_DIM)[c] = ev;
        float dx = ev.x - xv.x, dy = ev.y - xv.y, dz = ev.z - xv.z, dw = ev.w - xv.w;
        s += dx * dx + dy * dy + dz * dz + dw * dw;
    }
#pragma unroll
    for (int off = 16; off >= 1; off >>= 1)
        s += __shfl_xor_sync(0xffffffffu, s, off);
    if (lane == 0) {
        wsum[warp] = s;
        if (out_idx_f) out_idx_f[row] = (float)idx;
        if (out_idx_i) out_idx_i[row] = idx;
    }
    __syncthreads();
    if (threadIdx.x == 0) {
        float t = 0.f;
#pragma unroll
        for (int w = 0; w < 8; ++w) t += wsum[w];
        g_partial[blockIdx.x] = t;
    }
}

// ---------------------------------------------------------------------------
// Kernel F: loss = m + 0.25*m, m = sum/NQ.
// ---------------------------------------------------------------------------
__global__ void vq_loss_kernel(float* __restrict__ out_loss) {
    __shared__ float red[256];
    float s = 0.f;
#pragma unroll
    for (int t = 0; t < 8; ++t) s += g_partial[threadIdx.x + t * 256];
    red[threadIdx.x] = s;
    __syncthreads();
    for (int off = 128; off >= 1; off >>= 1) {
        if (threadIdx.x < off) red[threadIdx.x] += red[threadIdx.x + off];
        __syncthreads();
    }
    if (threadIdx.x == 0) {
        float m = red[0] / (float)NQ_ELEMS;
        *out_loss = m + 0.25f * m;
    }
}

// ---------------------------------------------------------------------------
extern "C" void kernel_launch(void* const* d_in, const int* in_sizes, int n_in,
                              void* d_out, int out_size) {
    const float* X = (const float*)d_in[0];
    const float* E = (const float*)d_in[1];
    float* out = (float*)d_out;

    float* out_q     = nullptr;
    float* out_loss  = nullptr;
    float* out_idx_f = nullptr;
    int*   out_idx_i = nullptr;

    if (out_size == NQ_ELEMS) {
        out_q = out;
    } else if (out_size == NQ_ELEMS + 1) {
        out_q = out; out_loss = out + NQ_ELEMS;
    } else if (out_size == NQ_ELEMS + 1 + N_ROWS) {
        out_q = out; out_loss = out + NQ_ELEMS; out_idx_f = out + NQ_ELEMS + 1;
    } else if (out_size == NQ_ELEMS + N_ROWS) {
        out_q = out; out_idx_f = out + NQ_ELEMS;
    } else if (out_size == N_ROWS) {
        out_idx_i = (int*)d_out;
    } else {
        out_q = out;
    }

    __nv_bfloat16 *dXb, *dEb;
    cudaGetSymbolAddress((void**)&dXb, g_Xb);
    cudaGetSymbolAddress((void**)&dEb, g_Eb);

    // A) bf16 copies
    vq_tobf16_kernel<<<NQ_ELEMS / 4 / 256, 256>>>(X, dXb, NQ_ELEMS / 4);
    vq_tobf16_kernel<<<K_EMB * D_DIM / 4 / 256, 256>>>(E, dEb, K_EMB * D_DIM / 4);

    // B) codebook norms + zero cand counters
    vq_enorm_kernel<<<K_EMB / 8, 256>>>(E);

    // C) coarse bf16 mma + candidate collection (2 CTAs/SM)
    const int smem_bytes = BM * XS * 2 + 2 * BN * ES * 2 + 2 * BN * 4 + BM * 4;
    cudaFuncSetAttribute(vq_coarse_kernel,
                         cudaFuncAttributeMaxDynamicSharedMemorySize, smem_bytes);
    dim3 grid(N_ROWS / BM, 2);
    vq_coarse_kernel<<<grid, NTHR, smem_bytes>>>();

    // D) exact fp32 rescue
    vq_rescue_kernel<<<N_ROWS / 8, 256>>>(X, E);

    // E) gather + partial loss sums
    vq_gather_kernel<<<N_ROWS / 8, 256>>>(X, E, out_q, out_idx_f, out_idx_i);

    // F) loss scalar
    if (out_loss) vq_loss_kernel<<<1, 256>>>(out_loss);
}